// round 15
// baseline (speedup 1.0000x reference)
#include <cuda_runtime.h>
#include <math.h>
#include <stdint.h>

#define B_ROWS   131072
#define NM       6
#define NP       30
#define WARPS    8
#define GRID     2048
#define RPW      (B_ROWS / (GRID * WARPS))   // 8 rows per warp
#define STRIDE   (GRID * WARPS)
#define STAGES   3

// 0 num_cls, 1 mgn_sum, 2 reg_loss, 3 num_reg,
// 4 a6x, 5 a6y, 6 f6x, 7 f6y, 8 a1x, 9 a1y, 10 f1x, 11 f1y
__device__ double g_acc[12];
__device__ unsigned int g_done;

struct __align__(16) Stage {
    float reg[360];   // 1440 B: one row of reg [6,30,2]
    float gt[64];     // 256 B: 60 used
};

__device__ __forceinline__ float warp_sum(float v) {
#pragma unroll
    for (int o = 16; o; o >>= 1) v += __shfl_xor_sync(0xffffffffu, v, o);
    return v;
}

__device__ __forceinline__ void cp16(uint32_t dst, const void* src) {
    asm volatile("cp.async.cg.shared.global [%0], [%1], 16;\n" :: "r"(dst), "l"(src));
}
__device__ __forceinline__ void cp_commit() {
    asm volatile("cp.async.commit_group;\n" ::: "memory");
}
__device__ __forceinline__ void cp_wait2() {
    asm volatile("cp.async.wait_group 2;\n" ::: "memory");
}

// order-preserving float->uint key
__device__ __forceinline__ unsigned fkey(float f) {
    unsigned b = __float_as_uint(f);
    return (b & 0x80000000u) ? ~b : (b | 0x80000000u);
}

__global__ void __launch_bounds__(256, 5) loss_main(
    const float* __restrict__ reg,
    const float* __restrict__ cls,
    const float* __restrict__ gt,
    const void*  __restrict__ has,
    float* __restrict__ out)
{
    __shared__ Stage st[WARPS][STAGES];
    __shared__ double blk[12];

    const int lane = threadIdx.x & 31;
    const int warp = threadIdx.x >> 5;
    if (threadIdx.x < 12) blk[threadIdx.x] = 0.0;
    __syncthreads();

    // detect storage width of bool array `has` (u8 vs 32-bit word)
    const unsigned w0 = *((const unsigned*)has);
    const bool hbyte = !(w0 == 0x3F800000u || w0 == 1u);

    const int wg = blockIdx.x * WARPS + warp;
    const float lm = (lane < NP) ? 1.f : 0.f;    // valid-timestep mask
    const int   t  = (lane < NP) ? lane : (NP - 1);
    const int   m6 = (lane < NM) ? lane : (NM - 1);   // clamped mode idx

    float a_numcls = 0.f, a_mgn = 0.f, a_regl = 0.f, a_numreg = 0.f;
    float a6x = 0.f, a6y = 0.f, f6x = 0.f, f6y = 0.f;
    float a1x = 0.f, a1y = 0.f, f1x = 0.f, f1y = 0.f;

    float hb[STAGES] = {0.f, 0.f, 0.f};
    float cb[STAGES] = {0.f, 0.f, 0.f};

    uint32_t sbase[STAGES];
#pragma unroll
    for (int i = 0; i < STAGES; i++)
        sbase[i] = (uint32_t)__cvta_generic_to_shared(&st[warp][i]);

    auto prefetch = [&](int it, int slot) {
        if (it < RPW) {
            const int row = wg + it * STRIDE;
            const uint32_t sb = sbase[slot];
            const char* rsrc = (const char*)(reg + (size_t)row * 360);
            cp16(sb + lane * 16,          rsrc + lane * 16);
            cp16(sb + (lane + 32) * 16,   rsrc + (lane + 32) * 16);
            if (lane < 26)
                cp16(sb + (lane + 64) * 16, rsrc + (lane + 64) * 16);
            if (lane < 15)
                cp16(sb + 1440 + lane * 16,
                     (const char*)(gt + (size_t)row * 60) + lane * 16);
            if (lane < NP) {
                size_t hidx = (size_t)row * NP + lane;
                unsigned v = hbyte ? (unsigned)((const unsigned char*)has)[hidx]
                                   : ((const unsigned*)has)[hidx];
                hb[slot] = v ? 1.f : 0.f;
            }
            if (lane < NM) cb[slot] = cls[(size_t)row * NM + lane];
        }
        cp_commit();
    };

    prefetch(0, 0);
    prefetch(1, 1);

#pragma unroll
    for (int it = 0; it < RPW; ++it) {
        const int slot = it % STAGES;
        prefetch(it + 2, (it + 2) % STAGES);   // keep 2 rows in flight

        // ====== PRE-WAIT: everything that needs only registers ======
        // has / last / valid (hv==0 for lanes>=NP by construction)
        const float hv = hb[slot];
        const unsigned bal = __ballot_sync(0xffffffffu, hv > 0.f) & 0x3FFFFFFFu;
        const int  last   = bal ? (31 - __clz(bal)) : (NP - 1);
        const bool valid  = (bal != 0u);
        const float validf = valid ? 1.0f : 0.0f;
        if (lane == 0) a_numreg += validf * (float)__popc(bal);

        // cls argmax (REDUX on register-resident cb)
        const float myc = cb[slot];
        const unsigned ckey = (lane < NM) ? fkey(myc) : 0u;
        const unsigned cmax = __reduce_max_sync(0xffffffffu, ckey);
        const unsigned tmask = __ballot_sync(0xffffffffu, ckey == cmax);
        const int top1 = __ffs(tmask) - 1;

        cp_wait2();                            // row `it` staged data ready
        __syncwarp();

        Stage& S = st[warp][slot];

        // ---- gt for lane t + clamped neighbors (LDS, no shuffles) ----
        const float2 gv = *(const float2*)&S.gt[2 * t];
        const float gx = gv.x, gy = gv.y;
        const float2 gp = *(const float2*)&S.gt[2 * ((t > 0) ? t - 1 : 0)];
        const float2 gn = *(const float2*)&S.gt[2 * ((t < NP - 1) ? t + 1 : NP - 1)];

        // moving flag (broadcast LDS)
        const float2 g0 = *(const float2*)&S.gt[0];
        const float2 gL = *(const float2*)&S.gt[2 * (NP - 1)];
        const float mdx = g0.x - gL.x, mdy = g0.y - gL.y;
        const bool moving = (mdx * mdx + mdy * mdy) > 4.0f;

        // ---- per-mode SQUARED distance at last point (no per-lane sqrt) ----
        const float2 gl = *(const float2*)&S.gt[2 * last];   // broadcast
        float d2own;
        {
            float2 rl = *(const float2*)&S.reg[m6 * 60 + 2 * last];
            float ddx = rl.x - gl.x, ddy = rl.y - gl.y;
            float d2 = ddx * ddx + ddy * ddy;
            d2own = (lane < NM) ? d2 : 1e30f;
        }

        // argmin over squared distance (nonneg: float bits order as uint)
        const unsigned dbits = __float_as_uint(d2own);
        const unsigned dmin  = __reduce_min_sync(0xffffffffu, dbits);
        const unsigned mmask = __ballot_sync(0xffffffffu, dbits == dmin);
        const int   min_idx  = __ffs(mmask) - 1;
        const float min_d2   = __uint_as_float(dmin);
        const float min_dist = sqrtf(min_d2);          // ONE uniform sqrt
        const float thr  = min_dist + 0.2f;
        const float thr2 = thr * thr;

        const float cls_min = __shfl_sync(0xffffffffu, myc, min_idx);
        {
            float mgn = cls_min - myc;
            bool cond = (lane < NM) && valid && (min_d2 < 4.0f) &&
                        (d2own > thr2) && (mgn < 0.2f);
            a_numcls += cond ? 1.0f : 0.0f;
            a_mgn    += cond ? mgn  : 0.0f;
        }

        // ---- heading: fully branch-free (selects only) ----
        float c, s;
        {
            float fdx = gn.x - gx, fdy = gn.y - gy;
            float bdx = gx - gp.x, bdy = gy - gp.y;
            float fr = fdx * fdx + fdy * fdy;
            float br = bdx * bdx + bdy * bdy;
            float fi = rsqrtf(fr), bi = rsqrtf(br);
            float cf = (fr > 0.f) ? fdx * fi : 1.f;
            float sf = (fr > 0.f) ? fdy * fi : 0.f;
            float cbw = (br > 0.f) ? bdx * bi : 1.f;
            float sbw = (br > 0.f) ? bdy * bi : 0.f;
            // endpoint override via select (bisector of (u,u) == u)
            if (lane == 0)      { cbw = cf;  sbw = sf; }
            if (lane == NP - 1) { cf = cbw;  sf = sbw; }

            float hx = cf + cbw, hy = sf + sbw;
            float dxx = cf - cbw, dyy = sf - sbw;
            float h2 = hx * hx + hy * hy;
            float d2 = dxx * dxx + dyy * dyy;
            const bool pick = (h2 >= d2);
            float inv = rsqrtf(pick ? h2 : d2);
            float cc = (pick ? hx : dyy) * inv;
            float ss = (pick ? -hy : dxx) * inv;
            c = moving ? cc : 1.f;
            s = moving ? ss : 0.f;
        }

        // ---- main sweep: all lanes, contributions masked by lm ----
        {
            float r6x = 0.f, r6y = 0.f;
#pragma unroll
            for (int k = 0; k < NM; k++) {
                float2 rv = *(const float2*)&S.reg[k * 60 + 2 * lane];
                float dx = fabsf(gx - rv.x);
                float dy = fabsf(gy - rv.y);
                float ex = fabsf(c * dx - s * dy);
                float ey = fabsf(s * dx + c * dy);
                r6x += ex; r6y += ey;
            }
            a6x += r6x * lm; a6y += r6y * lm;

            // top1 mode (warp-uniform index): ade1/fde1 terms
            float e1x, e1y;
            {
                float2 rv = *(const float2*)&S.reg[top1 * 60 + 2 * lane];
                float dx = fabsf(gx - rv.x);
                float dy = fabsf(gy - rv.y);
                e1x = fabsf(c * dx - s * dy);
                e1y = fabsf(s * dx + c * dy);
                a1x += e1x * lm; a1y += e1y * lm;
            }
            if (lane == NP - 1) {
                f6x += r6x; f6y += r6y;
                f1x += e1x; f1y += e1y;
            }

            // min-dist mode (warp-uniform index): SmoothL1 (w==0 masks lanes>=NP)
            {
                float2 rv = *(const float2*)&S.reg[min_idx * 60 + 2 * lane];
                float dx = fabsf(gx - rv.x);
                float dy = fabsf(gy - rv.y);
                float w  = hv * validf;
                float slx = (dx < 1.f) ? 0.5f * dx * dx : dx - 0.5f;
                float sly = (dy < 1.f) ? 0.5f * dy * dy : dy - 0.5f;
                a_regl += (slx + sly) * w;
            }
        }
        __syncwarp();   // WAR: this stage gets rewritten next iteration
    }

    // ---- reduction ----
    a_numcls = warp_sum(a_numcls);
    a_mgn    = warp_sum(a_mgn);
    a_regl   = warp_sum(a_regl);
    a_numreg = warp_sum(a_numreg);
    a6x = warp_sum(a6x); a6y = warp_sum(a6y);
    f6x = warp_sum(f6x); f6y = warp_sum(f6y);
    a1x = warp_sum(a1x); a1y = warp_sum(a1y);
    f1x = warp_sum(f1x); f1y = warp_sum(f1y);

    if (lane == 0) {
        atomicAdd(&blk[0],  (double)a_numcls);
        atomicAdd(&blk[1],  (double)a_mgn);
        atomicAdd(&blk[2],  (double)a_regl);
        atomicAdd(&blk[3],  (double)a_numreg);
        atomicAdd(&blk[4],  (double)a6x);
        atomicAdd(&blk[5],  (double)a6y);
        atomicAdd(&blk[6],  (double)f6x);
        atomicAdd(&blk[7],  (double)f6y);
        atomicAdd(&blk[8],  (double)a1x);
        atomicAdd(&blk[9],  (double)a1y);
        atomicAdd(&blk[10], (double)f1x);
        atomicAdd(&blk[11], (double)f1y);
    }
    __syncthreads();
    if (threadIdx.x < 12) {
        atomicAdd(&g_acc[threadIdx.x], blk[threadIdx.x]);
        __threadfence();
    }
    __syncthreads();

    if (threadIdx.x == 0) {
        unsigned done = atomicAdd(&g_done, 1u);
        if (done == GRID - 1) {
            __threadfence();
            double acc[12];
#pragma unroll
            for (int i = 0; i < 12; i++) acc[i] = *((volatile double*)&g_acc[i]);

            double num_cls  = acc[0];
            double mgn_sum  = acc[1];
            double reg_loss = acc[2];
            double num_reg  = acc[3];
            double cls_loss = 0.2 * num_cls - mgn_sum;
            double loss = cls_loss / (num_cls + 1e-10) + reg_loss / (num_reg + 1e-10);
            out[0]  = (float)loss;
            out[1]  = (float)cls_loss;
            out[2]  = (float)num_cls;
            out[3]  = (float)reg_loss;
            out[4]  = (float)num_reg;
            out[5]  = (float)acc[4];
            out[6]  = (float)acc[5];
            out[7]  = (float)acc[6];
            out[8]  = (float)acc[7];
            out[9]  = (float)(6.0 * (double)B_ROWS * 30.0);
            out[10] = (float)(6.0 * (double)B_ROWS);
            out[11] = (float)acc[8];
            out[12] = (float)acc[9];
            out[13] = (float)acc[10];
            out[14] = (float)acc[11];
            out[15] = (float)((double)B_ROWS * 30.0);
            out[16] = (float)B_ROWS;

#pragma unroll
            for (int i = 0; i < 12; i++) *((volatile double*)&g_acc[i]) = 0.0;
            __threadfence();
            atomicExch(&g_done, 0u);
        }
    }
}

extern "C" void kernel_launch(void* const* d_in, const int* in_sizes, int n_in,
                              void* d_out, int out_size) {
    const float* reg = nullptr;
    const float* cls = nullptr;
    const float* gt  = nullptr;
    const void*  has = nullptr;
    for (int i = 0; i < n_in; i++) {
        long long n = in_sizes[i];
        if (n == (long long)B_ROWS * NM * NP * 2)      reg = (const float*)d_in[i];
        else if (n == (long long)B_ROWS * NP * 2)      gt  = (const float*)d_in[i];
        else if (n == (long long)B_ROWS * NP)          has = d_in[i];
        else if (n == (long long)B_ROWS * NM)          cls = (const float*)d_in[i];
    }
    float* out = (float*)d_out;

    loss_main<<<GRID, 256>>>(reg, cls, gt, has, out);
}

// round 16
// speedup vs baseline: 1.0695x; 1.0695x over previous
#include <cuda_runtime.h>
#include <math.h>
#include <stdint.h>

#define B_ROWS   131072
#define NM       6
#define NP       30
#define WARPS    8
#define GRID     740                     // 148 SMs x 5 CTAs: ONE resident wave
#define NWARPS   (GRID * WARPS)          // 5920
#define RPW_LO   22                      // 5920*22 = 130240
#define REMW     (B_ROWS - NWARPS * RPW_LO)   // 832 warps take a 23rd row
#define STAGES   3

// 0 num_cls, 1 mgn_sum, 2 reg_loss, 3 num_reg,
// 4 a6x, 5 a6y, 6 f6x, 7 f6y, 8 a1x, 9 a1y, 10 f1x, 11 f1y
__device__ double g_acc[12];
__device__ unsigned int g_done;

struct __align__(16) Stage {
    float reg[360];   // 1440 B: one row of reg [6,30,2]
    float gt[64];     // 256 B: 60 used
};

__device__ __forceinline__ float warp_sum(float v) {
#pragma unroll
    for (int o = 16; o; o >>= 1) v += __shfl_xor_sync(0xffffffffu, v, o);
    return v;
}

__device__ __forceinline__ void cp16(uint32_t dst, const void* src) {
    asm volatile("cp.async.cg.shared.global [%0], [%1], 16;\n" :: "r"(dst), "l"(src));
}
__device__ __forceinline__ void cp_commit() {
    asm volatile("cp.async.commit_group;\n" ::: "memory");
}
__device__ __forceinline__ void cp_wait2() {
    asm volatile("cp.async.wait_group 2;\n" ::: "memory");
}

// order-preserving float->uint key
__device__ __forceinline__ unsigned fkey(float f) {
    unsigned b = __float_as_uint(f);
    return (b & 0x80000000u) ? ~b : (b | 0x80000000u);
}

__global__ void __launch_bounds__(256, 5) loss_main(
    const float* __restrict__ reg,
    const float* __restrict__ cls,
    const float* __restrict__ gt,
    const void*  __restrict__ has,
    float* __restrict__ out)
{
    __shared__ Stage st[WARPS][STAGES];
    __shared__ double blk[12];

    const int lane = threadIdx.x & 31;
    const int warp = threadIdx.x >> 5;
    if (threadIdx.x < 12) blk[threadIdx.x] = 0.0;
    __syncthreads();

    // detect storage width of bool array `has` (u8 vs 32-bit word)
    const unsigned w0 = *((const unsigned*)has);
    const bool hbyte = !(w0 == 0x3F800000u || w0 == 1u);

    const int wg = blockIdx.x * WARPS + warp;
    const int my_rpw = (wg < REMW) ? (RPW_LO + 1) : RPW_LO;   // 23 or 22
    const float lm = (lane < NP) ? 1.f : 0.f;    // valid-timestep mask
    const int   t  = (lane < NP) ? lane : (NP - 1);
    const int   m6 = (lane < NM) ? lane : (NM - 1);   // clamped mode idx

    float a_numcls = 0.f, a_mgn = 0.f, a_regl = 0.f, a_numreg = 0.f;
    float a6x = 0.f, a6y = 0.f, f6x = 0.f, f6y = 0.f;
    float a1x = 0.f, a1y = 0.f, f1x = 0.f, f1y = 0.f;

    float hb[STAGES] = {0.f, 0.f, 0.f};
    float cb[STAGES] = {0.f, 0.f, 0.f};

    uint32_t sbase[STAGES];
#pragma unroll
    for (int i = 0; i < STAGES; i++)
        sbase[i] = (uint32_t)__cvta_generic_to_shared(&st[warp][i]);

    auto prefetch = [&](const int it, const int slot) {
        if (it < my_rpw) {
            const int row = wg + it * NWARPS;
            const uint32_t sb = sbase[slot];
            const char* rsrc = (const char*)(reg + (size_t)row * 360);
            cp16(sb + lane * 16,          rsrc + lane * 16);
            cp16(sb + (lane + 32) * 16,   rsrc + (lane + 32) * 16);
            if (lane < 26)
                cp16(sb + (lane + 64) * 16, rsrc + (lane + 64) * 16);
            if (lane < 15)
                cp16(sb + 1440 + lane * 16,
                     (const char*)(gt + (size_t)row * 60) + lane * 16);
            if (lane < NP) {
                size_t hidx = (size_t)row * NP + lane;
                unsigned v = hbyte ? (unsigned)((const unsigned char*)has)[hidx]
                                   : ((const unsigned*)has)[hidx];
                hb[slot] = v ? 1.f : 0.f;
            }
            if (lane < NM) cb[slot] = cls[(size_t)row * NM + lane];
        }
        cp_commit();
    };

    // ---- full row body (R14 structure), compile-time slot ----
    auto body = [&](const int it, const int slot) {
        prefetch(it + 2, (slot + 2) % STAGES);  // constant-folds per call site
        cp_wait2();
        __syncwarp();

        Stage& S = st[warp][slot];

        // has / last / valid (hv==0 for lanes>=NP by construction)
        const float hv = hb[slot];
        const unsigned bal = __ballot_sync(0xffffffffu, hv > 0.f) & 0x3FFFFFFFu;
        const int  last   = bal ? (31 - __clz(bal)) : (NP - 1);
        const bool valid  = (bal != 0u);
        const float validf = valid ? 1.0f : 0.0f;
        if (lane == 0) a_numreg += validf * (float)__popc(bal);

        // gt for lane t + clamped neighbors (LDS, no shuffles)
        const float2 gv = *(const float2*)&S.gt[2 * t];
        const float gx = gv.x, gy = gv.y;
        const float2 gp = *(const float2*)&S.gt[2 * ((t > 0) ? t - 1 : 0)];
        const float2 gn = *(const float2*)&S.gt[2 * ((t < NP - 1) ? t + 1 : NP - 1)];

        // moving flag (broadcast LDS)
        const float2 g0 = *(const float2*)&S.gt[0];
        const float2 gL = *(const float2*)&S.gt[2 * (NP - 1)];
        const float mdx = g0.x - gL.x, mdy = g0.y - gL.y;
        const bool moving = (mdx * mdx + mdy * mdy) > 4.0f;

        // heading: fully branch-free (selects only)
        float c, s;
        {
            float fdx = gn.x - gx, fdy = gn.y - gy;
            float bdx = gx - gp.x, bdy = gy - gp.y;
            float fr = fdx * fdx + fdy * fdy;
            float br = bdx * bdx + bdy * bdy;
            float fi = rsqrtf(fr), bi = rsqrtf(br);
            float cf = (fr > 0.f) ? fdx * fi : 1.f;
            float sf = (fr > 0.f) ? fdy * fi : 0.f;
            float cbw = (br > 0.f) ? bdx * bi : 1.f;
            float sbw = (br > 0.f) ? bdy * bi : 0.f;
            if (lane == 0)      { cbw = cf;  sbw = sf; }
            if (lane == NP - 1) { cf = cbw;  sf = sbw; }

            float hx = cf + cbw, hy = sf + sbw;
            float dxx = cf - cbw, dyy = sf - sbw;
            float h2 = hx * hx + hy * hy;
            float d2 = dxx * dxx + dyy * dyy;
            const bool pick = (h2 >= d2);
            float inv = rsqrtf(pick ? h2 : d2);
            float cc = (pick ? hx : dyy) * inv;
            float ss = (pick ? -hy : dxx) * inv;
            c = moving ? cc : 1.f;
            s = moving ? ss : 0.f;
        }

        // per-mode distance at last point (clamped mode; select mask)
        const float2 gl = *(const float2*)&S.gt[2 * last];   // broadcast
        const float myc = cb[slot];
        float dstm;
        {
            float2 rl = *(const float2*)&S.reg[m6 * 60 + 2 * last];
            float ddx = rl.x - gl.x, ddy = rl.y - gl.y;
            float d = sqrtf(ddx * ddx + ddy * ddy);
            dstm = (lane < NM) ? d : 1e30f;
        }

        // argmin(dist) / argmax(cls) via HW REDUX
        const unsigned dbits = __float_as_uint(dstm);
        const unsigned dmin  = __reduce_min_sync(0xffffffffu, dbits);
        const unsigned mmask = __ballot_sync(0xffffffffu, dbits == dmin);
        const int   min_idx  = __ffs(mmask) - 1;
        const float min_dist = __uint_as_float(dmin);

        const unsigned ckey = (lane < NM) ? fkey(myc) : 0u;
        const unsigned cmax = __reduce_max_sync(0xffffffffu, ckey);
        const unsigned tmask = __ballot_sync(0xffffffffu, ckey == cmax);
        const int top1 = __ffs(tmask) - 1;

        const float cls_min = __shfl_sync(0xffffffffu, myc, min_idx);
        {
            float mgn = cls_min - myc;
            bool cond = (lane < NM) && valid && (min_dist < 2.0f) &&
                        ((dstm - min_dist) > 0.2f) && (mgn < 0.2f);
            a_numcls += cond ? 1.0f : 0.0f;
            a_mgn    += cond ? mgn  : 0.0f;
        }

        // main sweep: all lanes, contributions masked by lm
        {
            float r6x = 0.f, r6y = 0.f;
#pragma unroll
            for (int k = 0; k < NM; k++) {
                float2 rv = *(const float2*)&S.reg[k * 60 + 2 * lane];
                float dx = fabsf(gx - rv.x);
                float dy = fabsf(gy - rv.y);
                float ex = fabsf(c * dx - s * dy);
                float ey = fabsf(s * dx + c * dy);
                r6x += ex; r6y += ey;
            }
            a6x += r6x * lm; a6y += r6y * lm;

            float e1x, e1y;
            {
                float2 rv = *(const float2*)&S.reg[top1 * 60 + 2 * lane];
                float dx = fabsf(gx - rv.x);
                float dy = fabsf(gy - rv.y);
                e1x = fabsf(c * dx - s * dy);
                e1y = fabsf(s * dx + c * dy);
                a1x += e1x * lm; a1y += e1y * lm;
            }
            if (lane == NP - 1) {
                f6x += r6x; f6y += r6y;
                f1x += e1x; f1y += e1y;
            }

            {
                float2 rv = *(const float2*)&S.reg[min_idx * 60 + 2 * lane];
                float dx = fabsf(gx - rv.x);
                float dy = fabsf(gy - rv.y);
                float w  = hv * validf;
                float slx = (dx < 1.f) ? 0.5f * dx * dx : dx - 0.5f;
                float sly = (dy < 1.f) ? 0.5f * dy * dy : dy - 0.5f;
                a_regl += (slx + sly) * w;
            }
        }
        __syncwarp();   // WAR: this stage gets rewritten next time around
    };

    prefetch(0, 0);
    prefetch(1, 1);

    // triples keep slot indices compile-time; outer loop NOT unrolled
#pragma unroll 1
    for (int base = 0; base < RPW_LO + 2; base += 3) {
        body(base, 0);                             // base < my_rpw always holds
        if (base + 1 < my_rpw) body(base + 1, 1);  // warp-uniform guards
        if (base + 2 < my_rpw) body(base + 2, 2);
        if (base + 3 >= my_rpw) break;
    }

    // ---- reduction ----
    a_numcls = warp_sum(a_numcls);
    a_mgn    = warp_sum(a_mgn);
    a_regl   = warp_sum(a_regl);
    a_numreg = warp_sum(a_numreg);
    a6x = warp_sum(a6x); a6y = warp_sum(a6y);
    f6x = warp_sum(f6x); f6y = warp_sum(f6y);
    a1x = warp_sum(a1x); a1y = warp_sum(a1y);
    f1x = warp_sum(f1x); f1y = warp_sum(f1y);

    if (lane == 0) {
        atomicAdd(&blk[0],  (double)a_numcls);
        atomicAdd(&blk[1],  (double)a_mgn);
        atomicAdd(&blk[2],  (double)a_regl);
        atomicAdd(&blk[3],  (double)a_numreg);
        atomicAdd(&blk[4],  (double)a6x);
        atomicAdd(&blk[5],  (double)a6y);
        atomicAdd(&blk[6],  (double)f6x);
        atomicAdd(&blk[7],  (double)f6y);
        atomicAdd(&blk[8],  (double)a1x);
        atomicAdd(&blk[9],  (double)a1y);
        atomicAdd(&blk[10], (double)f1x);
        atomicAdd(&blk[11], (double)f1y);
    }
    __syncthreads();
    if (threadIdx.x < 12) {
        atomicAdd(&g_acc[threadIdx.x], blk[threadIdx.x]);
        __threadfence();
    }
    __syncthreads();

    if (threadIdx.x == 0) {
        unsigned done = atomicAdd(&g_done, 1u);
        if (done == GRID - 1) {
            __threadfence();
            double acc[12];
#pragma unroll
            for (int i = 0; i < 12; i++) acc[i] = *((volatile double*)&g_acc[i]);

            double num_cls  = acc[0];
            double mgn_sum  = acc[1];
            double reg_loss = acc[2];
            double num_reg  = acc[3];
            double cls_loss = 0.2 * num_cls - mgn_sum;
            double loss = cls_loss / (num_cls + 1e-10) + reg_loss / (num_reg + 1e-10);
            out[0]  = (float)loss;
            out[1]  = (float)cls_loss;
            out[2]  = (float)num_cls;
            out[3]  = (float)reg_loss;
            out[4]  = (float)num_reg;
            out[5]  = (float)acc[4];
            out[6]  = (float)acc[5];
            out[7]  = (float)acc[6];
            out[8]  = (float)acc[7];
            out[9]  = (float)(6.0 * (double)B_ROWS * 30.0);
            out[10] = (float)(6.0 * (double)B_ROWS);
            out[11] = (float)acc[8];
            out[12] = (float)acc[9];
            out[13] = (float)acc[10];
            out[14] = (float)acc[11];
            out[15] = (float)((double)B_ROWS * 30.0);
            out[16] = (float)B_ROWS;

#pragma unroll
            for (int i = 0; i < 12; i++) *((volatile double*)&g_acc[i]) = 0.0;
            __threadfence();
            atomicExch(&g_done, 0u);
        }
    }
}

extern "C" void kernel_launch(void* const* d_in, const int* in_sizes, int n_in,
                              void* d_out, int out_size) {
    const float* reg = nullptr;
    const float* cls = nullptr;
    const float* gt  = nullptr;
    const void*  has = nullptr;
    for (int i = 0; i < n_in; i++) {
        long long n = in_sizes[i];
        if (n == (long long)B_ROWS * NM * NP * 2)      reg = (const float*)d_in[i];
        else if (n == (long long)B_ROWS * NP * 2)      gt  = (const float*)d_in[i];
        else if (n == (long long)B_ROWS * NP)          has = d_in[i];
        else if (n == (long long)B_ROWS * NM)          cls = (const float*)d_in[i];
    }
    float* out = (float*)d_out;

    loss_main<<<GRID, 256>>>(reg, cls, gt, has, out);
}

// round 17
// speedup vs baseline: 1.1829x; 1.1061x over previous
#include <cuda_runtime.h>
#include <math.h>
#include <stdint.h>

#define B_ROWS   131072
#define NM       6
#define NP       30
#define WARPS    8
#define GRID     740                     // 148 SMs x 5 CTAs: ONE resident wave
#define NWARPS   (GRID * WARPS)          // 5920
#define RPW_LO   22                      // 5920*22 = 130240
#define REMW     (B_ROWS - NWARPS * RPW_LO)   // 832 warps take a 23rd row
#define STAGES   3

// 0 num_cls, 1 mgn_sum, 2 reg_loss, 3 num_reg,
// 4 a6x, 5 a6y, 6 f6x, 7 f6y, 8 a1x, 9 a1y, 10 f1x, 11 f1y
__device__ double g_acc[12];
__device__ unsigned int g_done;

struct __align__(16) Stage {
    float reg[360];   // 1440 B: one row of reg [6,30,2]
    float gt[64];     // 256 B: 60 used
};

__device__ __forceinline__ float warp_sum(float v) {
#pragma unroll
    for (int o = 16; o; o >>= 1) v += __shfl_xor_sync(0xffffffffu, v, o);
    return v;
}

__device__ __forceinline__ void cp16(uint32_t dst, const void* src) {
    asm volatile("cp.async.cg.shared.global [%0], [%1], 16;\n" :: "r"(dst), "l"(src));
}
__device__ __forceinline__ void cp_commit() {
    asm volatile("cp.async.commit_group;\n" ::: "memory");
}
__device__ __forceinline__ void cp_wait2() {
    asm volatile("cp.async.wait_group 2;\n" ::: "memory");
}

// order-preserving float->uint key
__device__ __forceinline__ unsigned fkey(float f) {
    unsigned b = __float_as_uint(f);
    return (b & 0x80000000u) ? ~b : (b | 0x80000000u);
}

__global__ void __launch_bounds__(256, 5) loss_main(
    const float* __restrict__ reg,
    const float* __restrict__ cls,
    const float* __restrict__ gt,
    const void*  __restrict__ has,
    float* __restrict__ out)
{
    __shared__ Stage st[WARPS][STAGES];
    __shared__ double blk[12];

    const int lane = threadIdx.x & 31;
    const int warp = threadIdx.x >> 5;
    if (threadIdx.x < 12) blk[threadIdx.x] = 0.0;
    __syncthreads();

    // detect storage width of bool array `has` (u8 vs 32-bit word)
    const unsigned w0 = *((const unsigned*)has);
    const bool hbyte = !(w0 == 0x3F800000u || w0 == 1u);

    const int wg = blockIdx.x * WARPS + warp;
    const int my_rpw = (wg < REMW) ? (RPW_LO + 1) : RPW_LO;   // 23 or 22
    const float lm = (lane < NP) ? 1.f : 0.f;    // valid-timestep mask
    const int   t  = (lane < NP) ? lane : (NP - 1);
    const int   m6 = (lane < NM) ? lane : (NM - 1);   // clamped mode idx

    float a_numcls = 0.f, a_mgn = 0.f, a_regl = 0.f, a_numreg = 0.f;
    float a6x = 0.f, a6y = 0.f, f6x = 0.f, f6y = 0.f;
    float a1x = 0.f, a1y = 0.f, f1x = 0.f, f1y = 0.f;

    float hb[STAGES] = {0.f, 0.f, 0.f};
    float cb[STAGES] = {0.f, 0.f, 0.f};

    uint32_t sbase[STAGES];
#pragma unroll
    for (int i = 0; i < STAGES; i++)
        sbase[i] = (uint32_t)__cvta_generic_to_shared(&st[warp][i]);

    auto prefetch = [&](const int it, const int slot) {
        if (it < my_rpw) {
            const int row = wg + it * NWARPS;
            const uint32_t sb = sbase[slot];
            const char* rsrc = (const char*)(reg + (size_t)row * 360);
            cp16(sb + lane * 16,          rsrc + lane * 16);
            cp16(sb + (lane + 32) * 16,   rsrc + (lane + 32) * 16);
            if (lane < 26)
                cp16(sb + (lane + 64) * 16, rsrc + (lane + 64) * 16);
            if (lane < 15)
                cp16(sb + 1440 + lane * 16,
                     (const char*)(gt + (size_t)row * 60) + lane * 16);
            if (lane < NP) {
                size_t hidx = (size_t)row * NP + lane;
                unsigned v = hbyte ? (unsigned)((const unsigned char*)has)[hidx]
                                   : ((const unsigned*)has)[hidx];
                hb[slot] = v ? 1.f : 0.f;
            }
            if (lane < NM) cb[slot] = cls[(size_t)row * NM + lane];
        }
        cp_commit();
    };

    // ---- full row body, compile-time slot ----
    auto body = [&](const int it, const int slot) {
        prefetch(it + 2, (slot + 2) % STAGES);  // constant-folds per call site
        cp_wait2();
        __syncwarp();

        Stage& S = st[warp][slot];

        // has / last / valid (hv==0 for lanes>=NP by construction)
        const float hv = hb[slot];
        const unsigned bal = __ballot_sync(0xffffffffu, hv > 0.f) & 0x3FFFFFFFu;
        const int  last   = bal ? (31 - __clz(bal)) : (NP - 1);
        const bool valid  = (bal != 0u);
        const float validf = valid ? 1.0f : 0.0f;
        if (lane == 0) a_numreg += validf * (float)__popc(bal);

        // gt for lane t (LDS)
        const float2 gv = *(const float2*)&S.gt[2 * t];
        const float gx = gv.x, gy = gv.y;

        // moving flag (broadcast LDS -> warp-uniform)
        const float2 g0 = *(const float2*)&S.gt[0];
        const float2 gL = *(const float2*)&S.gt[2 * (NP - 1)];
        const float mdx = g0.x - gL.x, mdy = g0.y - gL.y;
        const bool moving = (mdx * mdx + mdy * mdy) > 4.0f;

        // per-mode distance at last point (clamped mode; select mask)
        const float2 gl = *(const float2*)&S.gt[2 * last];   // broadcast
        const float myc = cb[slot];
        float dstm;
        {
            float2 rl = *(const float2*)&S.reg[m6 * 60 + 2 * last];
            float ddx = rl.x - gl.x, ddy = rl.y - gl.y;
            float d = sqrtf(ddx * ddx + ddy * ddy);
            dstm = (lane < NM) ? d : 1e30f;
        }

        // argmin(dist) / argmax(cls) via HW REDUX
        const unsigned dbits = __float_as_uint(dstm);
        const unsigned dmin  = __reduce_min_sync(0xffffffffu, dbits);
        const unsigned mmask = __ballot_sync(0xffffffffu, dbits == dmin);
        const int   min_idx  = __ffs(mmask) - 1;
        const float min_dist = __uint_as_float(dmin);

        const unsigned ckey = (lane < NM) ? fkey(myc) : 0u;
        const unsigned cmax = __reduce_max_sync(0xffffffffu, ckey);
        const unsigned tmask = __ballot_sync(0xffffffffu, ckey == cmax);
        const int top1 = __ffs(tmask) - 1;

        const float cls_min = __shfl_sync(0xffffffffu, myc, min_idx);
        {
            float mgn = cls_min - myc;
            bool cond = (lane < NM) && valid && (min_dist < 2.0f) &&
                        ((dstm - min_dist) > 0.2f) && (mgn < 0.2f);
            a_numcls += cond ? 1.0f : 0.0f;
            a_mgn    += cond ? mgn  : 0.0f;
        }

        const float w = hv * validf;

        if (moving) {
            // ---- heading (only needed on moving rows, ~37% of them) ----
            const float2 gp = *(const float2*)&S.gt[2 * ((t > 0) ? t - 1 : 0)];
            const float2 gn = *(const float2*)&S.gt[2 * ((t < NP - 1) ? t + 1 : NP - 1)];
            float c, s;
            {
                float fdx = gn.x - gx, fdy = gn.y - gy;
                float bdx = gx - gp.x, bdy = gy - gp.y;
                float fr = fdx * fdx + fdy * fdy;
                float br = bdx * bdx + bdy * bdy;
                float fi = rsqrtf(fr), bi = rsqrtf(br);
                float cf = (fr > 0.f) ? fdx * fi : 1.f;
                float sf = (fr > 0.f) ? fdy * fi : 0.f;
                float cbw = (br > 0.f) ? bdx * bi : 1.f;
                float sbw = (br > 0.f) ? bdy * bi : 0.f;
                if (lane == 0)      { cbw = cf;  sbw = sf; }
                if (lane == NP - 1) { cf = cbw;  sf = sbw; }

                float hx = cf + cbw, hy = sf + sbw;
                float dxx = cf - cbw, dyy = sf - sbw;
                float h2 = hx * hx + hy * hy;
                float d2 = dxx * dxx + dyy * dyy;
                const bool pick = (h2 >= d2);
                float inv = rsqrtf(pick ? h2 : d2);
                c = (pick ? hx : dyy) * inv;
                s = (pick ? -hy : dxx) * inv;
            }

            // rotated sweep
            float r6x = 0.f, r6y = 0.f;
#pragma unroll
            for (int k = 0; k < NM; k++) {
                float2 rv = *(const float2*)&S.reg[k * 60 + 2 * lane];
                float dx = fabsf(gx - rv.x);
                float dy = fabsf(gy - rv.y);
                float ex = fabsf(c * dx - s * dy);
                float ey = fabsf(s * dx + c * dy);
                r6x += ex; r6y += ey;
            }
            a6x += r6x * lm; a6y += r6y * lm;

            float e1x, e1y;
            {
                float2 rv = *(const float2*)&S.reg[top1 * 60 + 2 * lane];
                float dx = fabsf(gx - rv.x);
                float dy = fabsf(gy - rv.y);
                e1x = fabsf(c * dx - s * dy);
                e1y = fabsf(s * dx + c * dy);
                a1x += e1x * lm; a1y += e1y * lm;
            }
            if (lane == NP - 1) {
                f6x += r6x; f6y += r6y;
                f1x += e1x; f1y += e1y;
            }

            {
                float2 rv = *(const float2*)&S.reg[min_idx * 60 + 2 * lane];
                float dx = fabsf(gx - rv.x);
                float dy = fabsf(gy - rv.y);
                float slx = (dx < 1.f) ? 0.5f * dx * dx : dx - 0.5f;
                float sly = (dy < 1.f) ? 0.5f * dy * dy : dy - 0.5f;
                a_regl += (slx + sly) * w;
            }
        } else {
            // ---- c=1, s=0 exact specialization: plain L1 sweep ----
            float r6x = 0.f, r6y = 0.f;
#pragma unroll
            for (int k = 0; k < NM; k++) {
                float2 rv = *(const float2*)&S.reg[k * 60 + 2 * lane];
                r6x += fabsf(gx - rv.x);
                r6y += fabsf(gy - rv.y);
            }
            a6x += r6x * lm; a6y += r6y * lm;

            float e1x, e1y;
            {
                float2 rv = *(const float2*)&S.reg[top1 * 60 + 2 * lane];
                e1x = fabsf(gx - rv.x);
                e1y = fabsf(gy - rv.y);
                a1x += e1x * lm; a1y += e1y * lm;
            }
            if (lane == NP - 1) {
                f6x += r6x; f6y += r6y;
                f1x += e1x; f1y += e1y;
            }

            {
                float2 rv = *(const float2*)&S.reg[min_idx * 60 + 2 * lane];
                float dx = fabsf(gx - rv.x);
                float dy = fabsf(gy - rv.y);
                float slx = (dx < 1.f) ? 0.5f * dx * dx : dx - 0.5f;
                float sly = (dy < 1.f) ? 0.5f * dy * dy : dy - 0.5f;
                a_regl += (slx + sly) * w;
            }
        }
        __syncwarp();   // WAR: this stage gets rewritten next time around
    };

    prefetch(0, 0);
    prefetch(1, 1);

    // triples keep slot indices compile-time; outer loop NOT unrolled
#pragma unroll 1
    for (int base = 0; base < RPW_LO + 2; base += 3) {
        body(base, 0);                             // base < my_rpw always holds
        if (base + 1 < my_rpw) body(base + 1, 1);  // warp-uniform guards
        if (base + 2 < my_rpw) body(base + 2, 2);
        if (base + 3 >= my_rpw) break;
    }

    // ---- reduction ----
    a_numcls = warp_sum(a_numcls);
    a_mgn    = warp_sum(a_mgn);
    a_regl   = warp_sum(a_regl);
    a_numreg = warp_sum(a_numreg);
    a6x = warp_sum(a6x); a6y = warp_sum(a6y);
    f6x = warp_sum(f6x); f6y = warp_sum(f6y);
    a1x = warp_sum(a1x); a1y = warp_sum(a1y);
    f1x = warp_sum(f1x); f1y = warp_sum(f1y);

    if (lane == 0) {
        atomicAdd(&blk[0],  (double)a_numcls);
        atomicAdd(&blk[1],  (double)a_mgn);
        atomicAdd(&blk[2],  (double)a_regl);
        atomicAdd(&blk[3],  (double)a_numreg);
        atomicAdd(&blk[4],  (double)a6x);
        atomicAdd(&blk[5],  (double)a6y);
        atomicAdd(&blk[6],  (double)f6x);
        atomicAdd(&blk[7],  (double)f6y);
        atomicAdd(&blk[8],  (double)a1x);
        atomicAdd(&blk[9],  (double)a1y);
        atomicAdd(&blk[10], (double)f1x);
        atomicAdd(&blk[11], (double)f1y);
    }
    __syncthreads();
    if (threadIdx.x < 12) {
        atomicAdd(&g_acc[threadIdx.x], blk[threadIdx.x]);
        __threadfence();
    }
    __syncthreads();

    if (threadIdx.x == 0) {
        unsigned done = atomicAdd(&g_done, 1u);
        if (done == GRID - 1) {
            __threadfence();
            double acc[12];
#pragma unroll
            for (int i = 0; i < 12; i++) acc[i] = *((volatile double*)&g_acc[i]);

            double num_cls  = acc[0];
            double mgn_sum  = acc[1];
            double reg_loss = acc[2];
            double num_reg  = acc[3];
            double cls_loss = 0.2 * num_cls - mgn_sum;
            double loss = cls_loss / (num_cls + 1e-10) + reg_loss / (num_reg + 1e-10);
            out[0]  = (float)loss;
            out[1]  = (float)cls_loss;
            out[2]  = (float)num_cls;
            out[3]  = (float)reg_loss;
            out[4]  = (float)num_reg;
            out[5]  = (float)acc[4];
            out[6]  = (float)acc[5];
            out[7]  = (float)acc[6];
            out[8]  = (float)acc[7];
            out[9]  = (float)(6.0 * (double)B_ROWS * 30.0);
            out[10] = (float)(6.0 * (double)B_ROWS);
            out[11] = (float)acc[8];
            out[12] = (float)acc[9];
            out[13] = (float)acc[10];
            out[14] = (float)acc[11];
            out[15] = (float)((double)B_ROWS * 30.0);
            out[16] = (float)B_ROWS;

#pragma unroll
            for (int i = 0; i < 12; i++) *((volatile double*)&g_acc[i]) = 0.0;
            __threadfence();
            atomicExch(&g_done, 0u);
        }
    }
}

extern "C" void kernel_launch(void* const* d_in, const int* in_sizes, int n_in,
                              void* d_out, int out_size) {
    const float* reg = nullptr;
    const float* cls = nullptr;
    const float* gt  = nullptr;
    const void*  has = nullptr;
    for (int i = 0; i < n_in; i++) {
        long long n = in_sizes[i];
        if (n == (long long)B_ROWS * NM * NP * 2)      reg = (const float*)d_in[i];
        else if (n == (long long)B_ROWS * NP * 2)      gt  = (const float*)d_in[i];
        else if (n == (long long)B_ROWS * NP)          has = d_in[i];
        else if (n == (long long)B_ROWS * NM)          cls = (const float*)d_in[i];
    }
    float* out = (float*)d_out;

    loss_main<<<GRID, 256>>>(reg, cls, gt, has, out);
}